// round 10
// baseline (speedup 1.0000x reference)
#include <cuda_runtime.h>
#include <cstdint>

#define BATCH 64
#define TLEN 160
#define HID 256
#define MAXLEN 2000
#define FPB 8   // frames per block

// R2 geometry + bulk-async stores.
// Block = 8 consecutive frames of one batch. Gather rows via LDG, stage the
// 16KB (8x1KB out rows + 8x1KB pos rows, both contiguous in GMEM) in SMEM,
// then issue TWO cp.async.bulk stores (8KB each) instead of 32 STG.128.
__global__ __launch_bounds__(256) void lr_fused_kernel(
    const float* __restrict__ x,
    const float* __restrict__ penc,
    const int*   __restrict__ dur,
    float* __restrict__ out,
    float* __restrict__ pos,
    float* __restrict__ mel_out)
{
    __shared__ int s_csum[TLEN];
    __shared__ int s_tot[TLEN / 32];
    __shared__ __align__(16) float s_out[FPB * HID];   // 8KB
    __shared__ __align__(16) float s_pos[FPB * HID];   // 8KB

    const int b    = blockIdx.y;
    const int tid  = threadIdx.x;
    const int lane = tid & 31;
    const int warp = tid >> 5;

    // ---- in-block inclusive scan of duration[b, :] ----
    int v = 0;
    if (tid < TLEN) {
        v = __ldg(&dur[b * TLEN + tid]);
#pragma unroll
        for (int off = 1; off < 32; off <<= 1) {
            int n = __shfl_up_sync(0xffffffffu, v, off);
            if (lane >= off) v += n;
        }
        if (lane == 31) s_tot[warp] = v;
    }
    __syncthreads();
    if (tid < TLEN) {
        int add = 0;
#pragma unroll
        for (int i = 0; i < TLEN / 32; ++i)
            if (i < warp) add += s_tot[i];
        s_csum[tid] = v + add;
    }
    __syncthreads();

    const int mel = s_csum[TLEN - 1];
    if (blockIdx.x == 0 && tid == 0) mel_out[b] = (float)mel;

    // ---- one warp per frame: gather + stage into smem ----
    const int f = blockIdx.x * FPB + warp;
    const bool valid = (f < mel);

    float4 o0, o1, p0, p1;
    if (valid) {
        int lo = 0, hi = TLEN;
#pragma unroll 8
        while (lo < hi) {
            int mid = (lo + hi) >> 1;
            if (s_csum[mid] <= f) lo = mid + 1; else hi = mid;
        }
        int idx  = lo < (TLEN - 1) ? lo : (TLEN - 1);
        int excl = idx ? s_csum[idx - 1] : 0;
        int pw   = f - excl;

        const float4* xr = (const float4*)(x + ((size_t)b * TLEN + idx) * HID);
        const float4* pr = (const float4*)(penc + (size_t)pw * HID);
        o0 = xr[lane];  o1 = xr[lane + 32];
        p0 = pr[lane];  p1 = pr[lane + 32];
    } else {
        o0 = o1 = p0 = p1 = make_float4(0.f, 0.f, 0.f, 0.f);
    }

    float4* so = (float4*)s_out + warp * (HID / 4);
    float4* sp = (float4*)s_pos + warp * (HID / 4);
    so[lane]      = o0;
    so[lane + 32] = o1;
    sp[lane]      = p0;
    sp[lane + 32] = p1;
    __syncthreads();

    // ---- bulk-async stores: 2 x 8KB, issued by one thread ----
    if (tid == 0) {
        asm volatile("fence.proxy.async.shared::cta;" ::: "memory");

        uint32_t so_addr, sp_addr;
        asm("{ .reg .u64 t; cvta.to.shared.u64 t, %1; cvt.u32.u64 %0, t; }"
            : "=r"(so_addr) : "l"(s_out));
        asm("{ .reg .u64 t; cvta.to.shared.u64 t, %1; cvt.u32.u64 %0, t; }"
            : "=r"(sp_addr) : "l"(s_pos));

        const size_t rowbase = ((size_t)b * MAXLEN + (size_t)blockIdx.x * FPB) * HID;
        float* gout = out + rowbase;
        float* gpos = pos + rowbase;
        const uint32_t bytes = FPB * HID * 4;   // 8192

        asm volatile("cp.async.bulk.global.shared::cta.bulk_group [%0], [%1], %2;"
                     :: "l"(gout), "r"(so_addr), "r"(bytes) : "memory");
        asm volatile("cp.async.bulk.global.shared::cta.bulk_group [%0], [%1], %2;"
                     :: "l"(gpos), "r"(sp_addr), "r"(bytes) : "memory");
        asm volatile("cp.async.bulk.commit_group;" ::: "memory");
        // wait only until SMEM reads are done (writes drain independently)
        asm volatile("cp.async.bulk.wait_group.read 0;" ::: "memory");
    }
}

extern "C" void kernel_launch(void* const* d_in, const int* in_sizes, int n_in,
                              void* d_out, int out_size) {
    const float* x    = (const float*)d_in[0];   // (64,160,256) f32
    const float* penc = (const float*)d_in[1];   // (2001,256) f32
    const int*   dur  = (const int*)d_in[2];     // (64,160) int32
    // d_in[3] (max_len scalar) unused — fixed at 2000

    float* out = (float*)d_out;                                   // (64,2000,256)
    float* pos = out + (size_t)BATCH * MAXLEN * HID;              // (64,2000,256)
    float* mel = out + 2 * (size_t)BATCH * MAXLEN * HID;          // (64,)

    dim3 grid(MAXLEN / FPB, BATCH);
    lr_fused_kernel<<<grid, 256>>>(x, penc, dur, out, pos, mel);
}